// round 15
// baseline (speedup 1.0000x reference)
#include <cuda_runtime.h>
#include <cuda_fp16.h>
#include <cstdint>

#define THREADS  256        // 8 warps: warp grid 1m x 8n, warp tile 64x32
#define PTHREADS 256
#define TM       64         // batch rows per CTA
#define HID      256
#define INP      128
#define CAT      384
#define NCH      24         // K chunks of 16
#define CHW      2048       // uint32 words per chunk (256 n x 8 words)
#define AROWW    192        // words per A row (384 fp16), = 48 units of 16B
#define ZROWW    128        // words per z row (256 fp16)

// Pre-converted fp16 pair-interleaved weights.
// [zr combined: chunk c = 4096 words; word n*16 + 4*(p>>1) + (p&1) (+2 for Wr)]
// [Wh: 24 slots x 2048 words, word n*8 + p]; p (0..7) holds k-pair j = (p>>1)+(p&1)*4.
__device__ uint32_t wscratch[3 * NCH * CHW];

static __device__ __forceinline__ uint32_t smem_u32(const void* p) {
    uint32_t a;
    asm("{ .reg .u64 t; cvta.to.shared.u64 t, %1; cvt.u32.u64 %0, t; }" : "=r"(a) : "l"(p));
    return a;
}
static __device__ __forceinline__ uint32_t h2pack(float a, float b) {
    __half2 h = __floats2half2_rn(a, b);
    return *reinterpret_cast<uint32_t*>(&h);
}
static __device__ __forceinline__ float2 h2unpack(uint32_t u) {
    return __half22float2(*reinterpret_cast<__half2*>(&u));
}
static __device__ __forceinline__ void mma16(float* d, uint32_t a0, uint32_t a1,
                                             uint32_t a2, uint32_t a3,
                                             uint32_t b0, uint32_t b1) {
    asm volatile(
        "mma.sync.aligned.m16n8k16.row.col.f32.f16.f16.f32 "
        "{%0,%1,%2,%3}, {%4,%5,%6,%7}, {%8,%9}, {%0,%1,%2,%3};"
        : "+f"(d[0]), "+f"(d[1]), "+f"(d[2]), "+f"(d[3])
        : "r"(a0), "r"(a1), "r"(a2), "r"(a3), "r"(b0), "r"(b1));
}
// fp16-accumulator variant: D/C = 2 regs (half2 pairs), same element mapping as f32 d0..d3
static __device__ __forceinline__ void mma16h(uint32_t* d, const uint32_t (&a)[4],
                                              uint32_t b0, uint32_t b1) {
    asm volatile(
        "mma.sync.aligned.m16n8k16.row.col.f16.f16.f16.f16 "
        "{%0,%1}, {%2,%3,%4,%5}, {%6,%7}, {%0,%1};"
        : "+r"(d[0]), "+r"(d[1])
        : "r"(a[0]), "r"(a[1]), "r"(a[2]), "r"(a[3]), "r"(b0), "r"(b1));
}
static __device__ __forceinline__ void ldsm4(uint32_t (&a)[4], uint32_t saddr) {
    asm volatile("ldmatrix.sync.aligned.m8n8.x4.shared.b16 {%0,%1,%2,%3}, [%4];"
        : "=r"(a[0]), "=r"(a[1]), "=r"(a[2]), "=r"(a[3]) : "r"(saddr));
}
// z smem word offset: row rl, packed col zc (0..127), XOR swizzle keeps lanes conflict-free
static __device__ __forceinline__ int zoff(int rl, int zc) {
    return rl * ZROWW + (zc ^ ((rl & 7) << 2));
}

// ---------------- weight pre-conversion: fp32 -> fp16 images ----------------------------
__global__ void preconv_kernel(const float* __restrict__ Wz, const float* __restrict__ Wr,
                               const float* __restrict__ Wh) {
    int gid = blockIdx.x * PTHREADS + threadIdx.x;
    if (gid >= 3 * NCH * CHW) return;
    int w = gid / (NCH * CHW);
    int rem = gid - w * (NCH * CHW);
    int c = rem >> 11;            // / 2048
    int widx = rem & 2047;
    int n = widx >> 3;
    int p = widx & 7;
    int j = (p >> 1) + ((p & 1) << 2);
    int k = c * 16 + 2 * j;
    const float* W = (w == 0) ? Wz : (w == 1) ? Wr : Wh;
    uint32_t val = h2pack(W[(size_t)n * CAT + k], W[(size_t)n * CAT + k + 1]);
    size_t dst;
    if (w < 2)   // combined zr image: uint4 = (wz0, wz1, wr0, wr1) for (n, kq=p>>1)
        dst = (size_t)c * 4096 + n * 16 + 4 * (p >> 1) + (p & 1) + (w == 1 ? 2 : 0);
    else
        dst = (size_t)(2 * NCH) * CHW + (size_t)c * CHW + widx;
    wscratch[dst] = val;
}

#define UOFF(c) ((((2 * (c)) + usel) ^ l7) << 4)

// load the 4 combined zr fragments (uint4 = z-pair + r-pair) for one chunk
static __device__ __forceinline__ void ldb4(uint4 (&bf)[4], const uint4* __restrict__ p) {
    #pragma unroll
    for (int nt = 0; nt < 4; nt++) bf[nt] = __ldg(p + nt * 32);
}
// load the 4 B fragments (uint2) for one Wh chunk
static __device__ __forceinline__ void ldb(uint2 (&bf)[4], const uint2* __restrict__ p) {
    #pragma unroll
    for (int nt = 0; nt < 4; nt++) bf[nt] = __ldg(p + nt * 32);
}

// fused z+r chunk: one A fragment feeds 8 mma (4 z + 4 r), fp16 accumulators
static __device__ __forceinline__ void compute_chunk_zr(
    const uint32_t (&rowb)[4], uint32_t uoff_cur, uint32_t uoff_next,
    const uint4 (&bf)[4],
    uint32_t (&accz)[4][4][2], uint32_t (&accr)[4][4][2], uint32_t (&af)[4])
{
    uint32_t cur[4] = {af[0], af[1], af[2], af[3]};
    #pragma unroll
    for (int mt = 0; mt < 4; mt++) {
        uint32_t nxt[4];
        if (mt < 3) ldsm4(nxt, rowb[mt + 1] + uoff_cur);
        else        ldsm4(nxt, rowb[0] + uoff_next);
        #pragma unroll
        for (int nt = 0; nt < 4; nt++) {
            mma16h(accz[mt][nt], cur, bf[nt].x, bf[nt].y);
            mma16h(accr[mt][nt], cur, bf[nt].z, bf[nt].w);
        }
        cur[0] = nxt[0]; cur[1] = nxt[1]; cur[2] = nxt[2]; cur[3] = nxt[3];
    }
    af[0] = cur[0]; af[1] = cur[1]; af[2] = cur[2]; af[3] = cur[3];
}

// ---------------- fused z+r pass: combined LDG.128 B, 3 buffers, distance-2 -------------
static __device__ __forceinline__ void gemm_fused_zr(
    const uint32_t (&rowb)[4], uint32_t usel7, const uint32_t* __restrict__ wbase,
    uint32_t (&accz)[4][4][2], uint32_t (&accr)[4][4][2], int n0, int rq, int kq)
{
    #pragma unroll
    for (int mt = 0; mt < 4; mt++)
        #pragma unroll
        for (int nt = 0; nt < 4; nt++) {
            accz[mt][nt][0] = 0u; accz[mt][nt][1] = 0u;
            accr[mt][nt][0] = 0u; accr[mt][nt][1] = 0u;
        }

    // uint4 index for (chunk 0, n = n0+rq+nt*8, kq): word (n*16+4kq) / 4
    const uint4* __restrict__ Bg =
        reinterpret_cast<const uint4*>(wbase) + ((n0 + rq) * 4 + kq);
    const uint32_t usel = usel7 >> 8, l7 = usel7 & 7;

    uint4 b0[4], b1[4], b2[4];
    ldb4(b0, Bg);
    ldb4(b1, Bg + 1024);
    uint32_t af[4];
    ldsm4(af, rowb[0] + UOFF(0));

    #pragma unroll 1
    for (int cc = 0; cc < 8; cc++) {
        int c = cc * 3;
        if (c + 2 < NCH) ldb4(b2, Bg + (size_t)(c + 2) * 1024);
        compute_chunk_zr(rowb, UOFF(c), UOFF(c + 1), b0, accz, accr, af);
        if (c + 3 < NCH) ldb4(b0, Bg + (size_t)(c + 3) * 1024);
        compute_chunk_zr(rowb, UOFF(c + 1), UOFF(c + 2), b1, accz, accr, af);
        if (c + 4 < NCH) ldb4(b1, Bg + (size_t)(c + 4) * 1024);
        compute_chunk_zr(rowb, UOFF(c + 2), UOFF(c + 3 < NCH ? c + 3 : NCH - 1),
                         b2, accz, accr, af);
    }
}

// fp32-acc chunk (pass 3), A-fragment pipelined
static __device__ __forceinline__ void compute_chunk(
    const uint32_t (&rowb)[4], uint32_t uoff_cur, uint32_t uoff_next,
    const uint2 (&bf)[4], float (&acc)[4][4][4], uint32_t (&af)[4])
{
    uint32_t cur[4] = {af[0], af[1], af[2], af[3]};
    #pragma unroll
    for (int mt = 0; mt < 4; mt++) {
        uint32_t nxt[4];
        if (mt < 3) ldsm4(nxt, rowb[mt + 1] + uoff_cur);
        else        ldsm4(nxt, rowb[0] + uoff_next);
        #pragma unroll
        for (int nt = 0; nt < 4; nt++)
            mma16(acc[mt][nt], cur[0], cur[1], cur[2], cur[3], bf[nt].x, bf[nt].y);
        cur[0] = nxt[0]; cur[1] = nxt[1]; cur[2] = nxt[2]; cur[3] = nxt[3];
    }
    af[0] = cur[0]; af[1] = cur[1]; af[2] = cur[2]; af[3] = cur[3];
}

// ---------------- pass 3 GEMM: fp32 acc, 4 B buffers, distance-3 ------------------------
static __device__ __forceinline__ void gemm_pass(
    const uint32_t (&rowb)[4], uint32_t usel7, const uint32_t* __restrict__ wbase,
    float (&acc)[4][4][4], int n0, int rq, int kq)
{
    #pragma unroll
    for (int mt = 0; mt < 4; mt++)
        #pragma unroll
        for (int nt = 0; nt < 4; nt++)
            #pragma unroll
            for (int q = 0; q < 4; q++) acc[mt][nt][q] = 0.f;

    const uint2* __restrict__ Bg =
        reinterpret_cast<const uint2*>(wbase) + ((n0 + rq) * 4 + kq);
    const uint32_t usel = usel7 >> 8, l7 = usel7 & 7;

    uint2 b0[4], b1[4], b2[4], b3[4];
    ldb(b0, Bg);
    ldb(b1, Bg + 1024);
    ldb(b2, Bg + 2048);
    uint32_t af[4];
    ldsm4(af, rowb[0] + UOFF(0));

    #pragma unroll 1
    for (int cc = 0; cc < 6; cc++) {
        int c = cc * 4;
        if (c + 3 < NCH) ldb(b3, Bg + (size_t)(c + 3) * 1024);
        compute_chunk(rowb, UOFF(c + 0), UOFF(c + 1), b0, acc, af);
        if (c + 4 < NCH) ldb(b0, Bg + (size_t)(c + 4) * 1024);
        compute_chunk(rowb, UOFF(c + 1), UOFF(c + 2), b1, acc, af);
        if (c + 5 < NCH) ldb(b1, Bg + (size_t)(c + 5) * 1024);
        compute_chunk(rowb, UOFF(c + 2), UOFF(c + 3), b2, acc, af);
        if (c + 6 < NCH) ldb(b2, Bg + (size_t)(c + 6) * 1024);
        compute_chunk(rowb, UOFF(c + 3), UOFF(c + 4 < NCH ? c + 4 : NCH - 1), b3, acc, af);
    }
}

// ---------------- fused GRU kernel ------------------------------------------------------
__global__ void __launch_bounds__(THREADS, 2) gru_main_kernel(
    const float* __restrict__ x, const float* __restrict__ hp,
    const float* __restrict__ bz, const float* __restrict__ br,
    const float* __restrict__ bh, float* __restrict__ out)
{
    extern __shared__ uint32_t Asu[];         // 64 rows x 48 units(16B), unit u at u^(r&7)
    uint32_t* Zsu = Asu + TM * AROWW;         // 64*128 words (fp16x2 z stash)

    const int tid  = threadIdx.x;
    const int lane = tid & 31;
    const int warp = tid >> 5;
    const int n0   = warp * 32;
    const int rq   = lane >> 2;
    const int kq   = lane & 3;
    const int blockRow = blockIdx.x * TM;

    // ---- fill A smem: fp16(ih), natural k-order within 16B units, unit-XOR swizzle ----
    #pragma unroll 1
    for (int it = 0; it < 6; it++) {
        int idx = it * THREADS + tid;          // 0 .. 1535 groups
        int row = idx / 24;
        int g   = idx - row * 24;
        int k0  = g * 16;
        const float* src = (k0 < INP) ? (x + (size_t)(blockRow + row) * INP + k0)
                                      : (hp + (size_t)(blockRow + row) * HID + (k0 - INP));
        float4 v0 = *reinterpret_cast<const float4*>(src);
        float4 v1 = *reinterpret_cast<const float4*>(src + 4);
        float4 v2 = *reinterpret_cast<const float4*>(src + 8);
        float4 v3 = *reinterpret_cast<const float4*>(src + 12);
        uint4 u0, u1;
        u0.x = h2pack(v0.x, v0.y); u0.y = h2pack(v0.z, v0.w);
        u0.z = h2pack(v1.x, v1.y); u0.w = h2pack(v1.z, v1.w);
        u1.x = h2pack(v2.x, v2.y); u1.y = h2pack(v2.z, v2.w);
        u1.z = h2pack(v3.x, v3.y); u1.w = h2pack(v3.z, v3.w);
        int r7 = row & 7;
        int un = g * 2;
        *reinterpret_cast<uint4*>(Asu + row * AROWW + ((un ^ r7) << 2))       = u0;
        *reinterpret_cast<uint4*>(Asu + row * AROWW + (((un + 1) ^ r7) << 2)) = u1;
    }
    __syncthreads();

    uint32_t abase = smem_u32(Asu);
    uint32_t rowb[4];
    #pragma unroll
    for (int mt = 0; mt < 4; mt++)
        rowb[mt] = abase + (mt * 16 + (lane & 15)) * (AROWW * 4);
    const uint32_t usel7 = (((uint32_t)(lane >> 4) & 1) << 8) | (uint32_t)(lane & 7);

    // ================= fused pass: z & r preacts (fp16 acc) =============================
    {
        uint32_t accz[4][4][2], accr[4][4][2];
        gemm_fused_zr(rowb, usel7, wscratch, accz, accr, n0, rq, kq);

        // z epilogue -> Zsu (no A access; no sync needed yet)
        #pragma unroll
        for (int mt = 0; mt < 4; mt++) {
            int rl = mt * 16 + rq;
            #pragma unroll
            for (int nt = 0; nt < 4; nt++) {
                int cb = n0 + nt * 8 + (kq << 1);
                float2 bv = *reinterpret_cast<const float2*>(bz + cb);
                float2 v0 = h2unpack(accz[mt][nt][0]);   // row rl,  cols cb, cb+1
                float2 v1 = h2unpack(accz[mt][nt][1]);   // row rl+8
                float z0 = __saturatef((v0.x + bv.x) * 0.16666667f + 0.5f);
                float z1 = __saturatef((v0.y + bv.y) * 0.16666667f + 0.5f);
                float z2 = __saturatef((v1.x + bv.x) * 0.16666667f + 0.5f);
                float z3 = __saturatef((v1.y + bv.y) * 0.16666667f + 0.5f);
                int zc = (cb >> 1);
                Zsu[zoff(rl, zc)]     = h2pack(z0, z1);
                Zsu[zoff(rl + 8, zc)] = h2pack(z2, z3);
            }
        }

        __syncthreads();   // all warps done reading A in fused pass

        // r epilogue: A_h := fp16(r * h)
        #pragma unroll
        for (int mt = 0; mt < 4; mt++) {
            int rl = mt * 16 + rq;
            int r7 = rl & 7;
            #pragma unroll
            for (int nt = 0; nt < 4; nt++) {
                int cb = n0 + nt * 8 + (kq << 1);
                float2 bv = *reinterpret_cast<const float2*>(br + cb);
                float2 v0 = h2unpack(accr[mt][nt][0]);
                float2 v1 = h2unpack(accr[mt][nt][1]);
                float r0 = __saturatef((v0.x + bv.x) * 0.16666667f + 0.5f);
                float r1 = __saturatef((v0.y + bv.y) * 0.16666667f + 0.5f);
                float r2 = __saturatef((v1.x + bv.x) * 0.16666667f + 0.5f);
                float r3 = __saturatef((v1.y + bv.y) * 0.16666667f + 0.5f);
                float2 h0 = *reinterpret_cast<const float2*>(hp + (size_t)(blockRow + rl) * HID + cb);
                float2 h1 = *reinterpret_cast<const float2*>(hp + (size_t)(blockRow + rl + 8) * HID + cb);
                int un = (INP + n0 + nt * 8) >> 3;
                int wo = ((un ^ r7) << 2) + kq;
                Asu[rl * AROWW + wo]       = h2pack(r0 * h0.x, r1 * h0.y);
                Asu[(rl + 8) * AROWW + wo] = h2pack(r2 * h1.x, r3 * h1.y);
            }
        }
    }
    __syncthreads();

    // ================= pass 3: htilde (fp32 acc); h_next = z*h + (1-z)*hardtanh(.) ======
    float acc[4][4][4];
    gemm_pass(rowb, usel7, wscratch + 2 * NCH * CHW, acc, n0, rq, kq);
    #pragma unroll
    for (int mt = 0; mt < 4; mt++) {
        int rl = mt * 16 + rq;
        #pragma unroll
        for (int nt = 0; nt < 4; nt++) {
            int cb = n0 + nt * 8 + (kq << 1);
            float2 bv = *reinterpret_cast<const float2*>(bh + cb);
            size_t o0 = (size_t)(blockRow + rl) * HID + cb;
            size_t o1 = (size_t)(blockRow + rl + 8) * HID + cb;
            int zc = (cb >> 1);
            float2 zz0 = h2unpack(Zsu[zoff(rl, zc)]);
            float2 zz1 = h2unpack(Zsu[zoff(rl + 8, zc)]);
            float2 hh0 = *reinterpret_cast<const float2*>(hp + o0);
            float2 hh1 = *reinterpret_cast<const float2*>(hp + o1);
            float t0 = fminf(fmaxf(acc[mt][nt][0] + bv.x, -1.f), 1.f);
            float t1 = fminf(fmaxf(acc[mt][nt][1] + bv.y, -1.f), 1.f);
            float t2 = fminf(fmaxf(acc[mt][nt][2] + bv.x, -1.f), 1.f);
            float t3 = fminf(fmaxf(acc[mt][nt][3] + bv.y, -1.f), 1.f);
            float2 r0, r1;
            r0.x = zz0.x * hh0.x + (1.f - zz0.x) * t0;
            r0.y = zz0.y * hh0.y + (1.f - zz0.y) * t1;
            r1.x = zz1.x * hh1.x + (1.f - zz1.x) * t2;
            r1.y = zz1.y * hh1.y + (1.f - zz1.y) * t3;
            *reinterpret_cast<float2*>(out + o0) = r0;
            *reinterpret_cast<float2*>(out + o1) = r1;
        }
    }
}

extern "C" void kernel_launch(void* const* d_in, const int* in_sizes, int n_in,
                              void* d_out, int out_size) {
    const float* x  = (const float*)d_in[0];
    const float* hp = (const float*)d_in[1];
    const float* Wz = (const float*)d_in[2];
    const float* bz = (const float*)d_in[3];
    const float* Wr = (const float*)d_in[4];
    const float* br = (const float*)d_in[5];
    const float* Wh = (const float*)d_in[6];
    const float* bh = (const float*)d_in[7];
    float* out = (float*)d_out;

    preconv_kernel<<<(3 * NCH * CHW + PTHREADS - 1) / PTHREADS, PTHREADS>>>(Wz, Wr, Wh);

    int batch = in_sizes[0] / INP;
    int grid = batch / TM;
    size_t smem = (size_t)(TM * AROWW + TM * ZROWW) * 4;   // 81920 B = 80 KB
    cudaFuncSetAttribute(gru_main_kernel,
                         cudaFuncAttributeMaxDynamicSharedMemorySize, (int)smem);
    gru_main_kernel<<<grid, THREADS, smem>>>(x, hp, bz, br, bh, out);
}

// round 16
// speedup vs baseline: 1.0484x; 1.0484x over previous
#include <cuda_runtime.h>
#include <cuda_fp16.h>
#include <cstdint>

#define THREADS  256        // 8 warps: warp grid 1m x 8n, warp tile 64x32
#define PTHREADS 256
#define TM       64         // batch rows per CTA
#define HID      256
#define INP      128
#define CAT      384
#define NCH      24         // K chunks of 16
#define CHW      2048       // uint32 words per chunk (256 n x 8 words)
#define AROWW    192        // words per A row (384 fp16), = 48 units of 16B
#define ZROWW    128        // words per z row (256 fp16)

// Pre-converted fp16 pair-interleaved weights.
// [zr combined: chunk c = 4096 words; word n*16 + 4*(p>>1) + (p&1) (+2 for Wr)]
// [Wh: 24 slots x 2048 words, word n*8 + p]; p (0..7) holds k-pair j = (p>>1)+(p&1)*4.
__device__ uint32_t wscratch[3 * NCH * CHW];

static __device__ __forceinline__ uint32_t smem_u32(const void* p) {
    uint32_t a;
    asm("{ .reg .u64 t; cvta.to.shared.u64 t, %1; cvt.u32.u64 %0, t; }" : "=r"(a) : "l"(p));
    return a;
}
static __device__ __forceinline__ uint32_t h2pack(float a, float b) {
    __half2 h = __floats2half2_rn(a, b);
    return *reinterpret_cast<uint32_t*>(&h);
}
static __device__ __forceinline__ float2 h2unpack(uint32_t u) {
    return __half22float2(*reinterpret_cast<__half2*>(&u));
}
static __device__ __forceinline__ void mma16(float* d, uint32_t a0, uint32_t a1,
                                             uint32_t a2, uint32_t a3,
                                             uint32_t b0, uint32_t b1) {
    asm volatile(
        "mma.sync.aligned.m16n8k16.row.col.f32.f16.f16.f32 "
        "{%0,%1,%2,%3}, {%4,%5,%6,%7}, {%8,%9}, {%0,%1,%2,%3};"
        : "+f"(d[0]), "+f"(d[1]), "+f"(d[2]), "+f"(d[3])
        : "r"(a0), "r"(a1), "r"(a2), "r"(a3), "r"(b0), "r"(b1));
}
// fp16-accumulator variant: D/C = 2 regs (half2 pairs), same element mapping as f32 d0..d3
static __device__ __forceinline__ void mma16h(uint32_t* d, const uint32_t (&a)[4],
                                              uint32_t b0, uint32_t b1) {
    asm volatile(
        "mma.sync.aligned.m16n8k16.row.col.f16.f16.f16.f16 "
        "{%0,%1}, {%2,%3,%4,%5}, {%6,%7}, {%0,%1};"
        : "+r"(d[0]), "+r"(d[1])
        : "r"(a[0]), "r"(a[1]), "r"(a[2]), "r"(a[3]), "r"(b0), "r"(b1));
}
static __device__ __forceinline__ void ldsm4(uint32_t (&a)[4], uint32_t saddr) {
    asm volatile("ldmatrix.sync.aligned.m8n8.x4.shared.b16 {%0,%1,%2,%3}, [%4];"
        : "=r"(a[0]), "=r"(a[1]), "=r"(a[2]), "=r"(a[3]) : "r"(saddr));
}
// z smem word offset: row rl, packed col zc (0..127), XOR swizzle keeps lanes conflict-free
static __device__ __forceinline__ int zoff(int rl, int zc) {
    return rl * ZROWW + (zc ^ ((rl & 7) << 2));
}

// ---------------- weight pre-conversion: fp32 -> fp16 images ----------------------------
__global__ void preconv_kernel(const float* __restrict__ Wz, const float* __restrict__ Wr,
                               const float* __restrict__ Wh) {
    int gid = blockIdx.x * PTHREADS + threadIdx.x;
    if (gid >= 3 * NCH * CHW) return;
    int w = gid / (NCH * CHW);
    int rem = gid - w * (NCH * CHW);
    int c = rem >> 11;            // / 2048
    int widx = rem & 2047;
    int n = widx >> 3;
    int p = widx & 7;
    int j = (p >> 1) + ((p & 1) << 2);
    int k = c * 16 + 2 * j;
    const float* W = (w == 0) ? Wz : (w == 1) ? Wr : Wh;
    uint32_t val = h2pack(W[(size_t)n * CAT + k], W[(size_t)n * CAT + k + 1]);
    size_t dst;
    if (w < 2)   // combined zr image: uint4 = (wz0, wz1, wr0, wr1) for (n, kq=p>>1)
        dst = (size_t)c * 4096 + n * 16 + 4 * (p >> 1) + (p & 1) + (w == 1 ? 2 : 0);
    else
        dst = (size_t)(2 * NCH) * CHW + (size_t)c * CHW + widx;
    wscratch[dst] = val;
}

#define UOFF(c) ((((2 * (c)) + usel) ^ l7) << 4)

// load the 4 combined zr fragments (uint4 = z-pair + r-pair) for one chunk
static __device__ __forceinline__ void ldb4(uint4 (&bf)[4], const uint4* __restrict__ p) {
    #pragma unroll
    for (int nt = 0; nt < 4; nt++) bf[nt] = __ldg(p + nt * 32);
}
// load the 4 B fragments (uint2) for one Wh chunk
static __device__ __forceinline__ void ldb(uint2 (&bf)[4], const uint2* __restrict__ p) {
    #pragma unroll
    for (int nt = 0; nt < 4; nt++) bf[nt] = __ldg(p + nt * 32);
}

// fused z+r chunk: one A fragment feeds 8 mma (4 z + 4 r), fp16 accumulators
static __device__ __forceinline__ void compute_chunk_zr(
    const uint32_t (&rowb)[4], uint32_t uoff_cur, uint32_t uoff_next,
    const uint4 (&bf)[4],
    uint32_t (&accz)[4][4][2], uint32_t (&accr)[4][4][2], uint32_t (&af)[4])
{
    uint32_t cur[4] = {af[0], af[1], af[2], af[3]};
    #pragma unroll
    for (int mt = 0; mt < 4; mt++) {
        uint32_t nxt[4];
        if (mt < 3) ldsm4(nxt, rowb[mt + 1] + uoff_cur);
        else        ldsm4(nxt, rowb[0] + uoff_next);
        #pragma unroll
        for (int nt = 0; nt < 4; nt++) {
            mma16h(accz[mt][nt], cur, bf[nt].x, bf[nt].y);
            mma16h(accr[mt][nt], cur, bf[nt].z, bf[nt].w);
        }
        cur[0] = nxt[0]; cur[1] = nxt[1]; cur[2] = nxt[2]; cur[3] = nxt[3];
    }
    af[0] = cur[0]; af[1] = cur[1]; af[2] = cur[2]; af[3] = cur[3];
}

// ---------------- fused z+r pass: combined LDG.128 B, 2 buffers (R14 structure) ---------
static __device__ __forceinline__ void gemm_fused_zr(
    const uint32_t (&rowb)[4], uint32_t usel7, const uint32_t* __restrict__ wbase,
    uint32_t (&accz)[4][4][2], uint32_t (&accr)[4][4][2], int n0, int rq, int kq)
{
    #pragma unroll
    for (int mt = 0; mt < 4; mt++)
        #pragma unroll
        for (int nt = 0; nt < 4; nt++) {
            accz[mt][nt][0] = 0u; accz[mt][nt][1] = 0u;
            accr[mt][nt][0] = 0u; accr[mt][nt][1] = 0u;
        }

    // uint4 index for (chunk 0, n = n0+rq+nt*8, kq): word (n*16+4kq) / 4
    const uint4* __restrict__ Bg =
        reinterpret_cast<const uint4*>(wbase) + ((n0 + rq) * 4 + kq);
    const uint32_t usel = usel7 >> 8, l7 = usel7 & 7;

    uint4 b0[4], b1[4];
    ldb4(b0, Bg);
    uint32_t af[4];
    ldsm4(af, rowb[0] + UOFF(0));

    #pragma unroll 1
    for (int cc = 0; cc < 12; cc++) {
        int c = cc * 2;
        if (c + 1 < NCH) ldb4(b1, Bg + (size_t)(c + 1) * 1024);
        compute_chunk_zr(rowb, UOFF(c), UOFF(c + 1), b0, accz, accr, af);
        if (c + 2 < NCH) ldb4(b0, Bg + (size_t)(c + 2) * 1024);
        compute_chunk_zr(rowb, UOFF(c + 1), UOFF(c + 2 < NCH ? c + 2 : NCH - 1),
                         b1, accz, accr, af);
    }
}

// fp32-acc chunk (pass 3), A-fragment pipelined
static __device__ __forceinline__ void compute_chunk(
    const uint32_t (&rowb)[4], uint32_t uoff_cur, uint32_t uoff_next,
    const uint2 (&bf)[4], float (&acc)[4][4][4], uint32_t (&af)[4])
{
    uint32_t cur[4] = {af[0], af[1], af[2], af[3]};
    #pragma unroll
    for (int mt = 0; mt < 4; mt++) {
        uint32_t nxt[4];
        if (mt < 3) ldsm4(nxt, rowb[mt + 1] + uoff_cur);
        else        ldsm4(nxt, rowb[0] + uoff_next);
        #pragma unroll
        for (int nt = 0; nt < 4; nt++)
            mma16(acc[mt][nt], cur[0], cur[1], cur[2], cur[3], bf[nt].x, bf[nt].y);
        cur[0] = nxt[0]; cur[1] = nxt[1]; cur[2] = nxt[2]; cur[3] = nxt[3];
    }
    af[0] = cur[0]; af[1] = cur[1]; af[2] = cur[2]; af[3] = cur[3];
}

// ---------------- pass 3 GEMM: fp32 acc, 4 B buffers, distance-3 ------------------------
static __device__ __forceinline__ void gemm_pass(
    const uint32_t (&rowb)[4], uint32_t usel7, const uint32_t* __restrict__ wbase,
    float (&acc)[4][4][4], int n0, int rq, int kq)
{
    #pragma unroll
    for (int mt = 0; mt < 4; mt++)
        #pragma unroll
        for (int nt = 0; nt < 4; nt++)
            #pragma unroll
            for (int q = 0; q < 4; q++) acc[mt][nt][q] = 0.f;

    const uint2* __restrict__ Bg =
        reinterpret_cast<const uint2*>(wbase) + ((n0 + rq) * 4 + kq);
    const uint32_t usel = usel7 >> 8, l7 = usel7 & 7;

    uint2 b0[4], b1[4], b2[4], b3[4];
    ldb(b0, Bg);
    ldb(b1, Bg + 1024);
    ldb(b2, Bg + 2048);
    uint32_t af[4];
    ldsm4(af, rowb[0] + UOFF(0));

    #pragma unroll 1
    for (int cc = 0; cc < 6; cc++) {
        int c = cc * 4;
        if (c + 3 < NCH) ldb(b3, Bg + (size_t)(c + 3) * 1024);
        compute_chunk(rowb, UOFF(c + 0), UOFF(c + 1), b0, acc, af);
        if (c + 4 < NCH) ldb(b0, Bg + (size_t)(c + 4) * 1024);
        compute_chunk(rowb, UOFF(c + 1), UOFF(c + 2), b1, acc, af);
        if (c + 5 < NCH) ldb(b1, Bg + (size_t)(c + 5) * 1024);
        compute_chunk(rowb, UOFF(c + 2), UOFF(c + 3), b2, acc, af);
        if (c + 6 < NCH) ldb(b2, Bg + (size_t)(c + 6) * 1024);
        compute_chunk(rowb, UOFF(c + 3), UOFF(c + 4 < NCH ? c + 4 : NCH - 1), b3, acc, af);
    }
}

// ---------------- fused GRU kernel ------------------------------------------------------
__global__ void __launch_bounds__(THREADS, 2) gru_main_kernel(
    const float* __restrict__ x, const float* __restrict__ hp,
    const float* __restrict__ bz, const float* __restrict__ br,
    const float* __restrict__ bh, float* __restrict__ out)
{
    extern __shared__ uint32_t Asu[];         // 64 rows x 48 units(16B), unit u at u^(r&7)
    uint32_t* Zsu = Asu + TM * AROWW;         // 64*128 words (fp16x2 z stash)

    const int tid  = threadIdx.x;
    const int lane = tid & 31;
    const int warp = tid >> 5;
    const int n0   = warp * 32;
    const int rq   = lane >> 2;
    const int kq   = lane & 3;
    const int blockRow = blockIdx.x * TM;

    // ---- fill A smem: fp16(ih), natural k-order within 16B units, unit-XOR swizzle ----
    #pragma unroll 1
    for (int it = 0; it < 6; it++) {
        int idx = it * THREADS + tid;          // 0 .. 1535 groups
        int row = idx / 24;
        int g   = idx - row * 24;
        int k0  = g * 16;
        const float* src = (k0 < INP) ? (x + (size_t)(blockRow + row) * INP + k0)
                                      : (hp + (size_t)(blockRow + row) * HID + (k0 - INP));
        float4 v0 = *reinterpret_cast<const float4*>(src);
        float4 v1 = *reinterpret_cast<const float4*>(src + 4);
        float4 v2 = *reinterpret_cast<const float4*>(src + 8);
        float4 v3 = *reinterpret_cast<const float4*>(src + 12);
        uint4 u0, u1;
        u0.x = h2pack(v0.x, v0.y); u0.y = h2pack(v0.z, v0.w);
        u0.z = h2pack(v1.x, v1.y); u0.w = h2pack(v1.z, v1.w);
        u1.x = h2pack(v2.x, v2.y); u1.y = h2pack(v2.z, v2.w);
        u1.z = h2pack(v3.x, v3.y); u1.w = h2pack(v3.z, v3.w);
        int r7 = row & 7;
        int un = g * 2;
        *reinterpret_cast<uint4*>(Asu + row * AROWW + ((un ^ r7) << 2))       = u0;
        *reinterpret_cast<uint4*>(Asu + row * AROWW + (((un + 1) ^ r7) << 2)) = u1;
    }
    __syncthreads();

    uint32_t abase = smem_u32(Asu);
    uint32_t rowb[4];
    #pragma unroll
    for (int mt = 0; mt < 4; mt++)
        rowb[mt] = abase + (mt * 16 + (lane & 15)) * (AROWW * 4);
    const uint32_t usel7 = (((uint32_t)(lane >> 4) & 1) << 8) | (uint32_t)(lane & 7);

    // ================= fused pass: z & r preacts (fp16 acc) =============================
    {
        uint32_t accz[4][4][2], accr[4][4][2];
        gemm_fused_zr(rowb, usel7, wscratch, accz, accr, n0, rq, kq);

        // z epilogue -> Zsu (no A access; no sync needed yet)
        #pragma unroll
        for (int mt = 0; mt < 4; mt++) {
            int rl = mt * 16 + rq;
            #pragma unroll
            for (int nt = 0; nt < 4; nt++) {
                int cb = n0 + nt * 8 + (kq << 1);
                float2 bv = *reinterpret_cast<const float2*>(bz + cb);
                float2 v0 = h2unpack(accz[mt][nt][0]);   // row rl,  cols cb, cb+1
                float2 v1 = h2unpack(accz[mt][nt][1]);   // row rl+8
                float z0 = __saturatef((v0.x + bv.x) * 0.16666667f + 0.5f);
                float z1 = __saturatef((v0.y + bv.y) * 0.16666667f + 0.5f);
                float z2 = __saturatef((v1.x + bv.x) * 0.16666667f + 0.5f);
                float z3 = __saturatef((v1.y + bv.y) * 0.16666667f + 0.5f);
                int zc = (cb >> 1);
                Zsu[zoff(rl, zc)]     = h2pack(z0, z1);
                Zsu[zoff(rl + 8, zc)] = h2pack(z2, z3);
            }
        }

        __syncthreads();   // all warps done reading A in fused pass

        // r epilogue: A_h := fp16(r * h)
        #pragma unroll
        for (int mt = 0; mt < 4; mt++) {
            int rl = mt * 16 + rq;
            int r7 = rl & 7;
            #pragma unroll
            for (int nt = 0; nt < 4; nt++) {
                int cb = n0 + nt * 8 + (kq << 1);
                float2 bv = *reinterpret_cast<const float2*>(br + cb);
                float2 v0 = h2unpack(accr[mt][nt][0]);
                float2 v1 = h2unpack(accr[mt][nt][1]);
                float r0 = __saturatef((v0.x + bv.x) * 0.16666667f + 0.5f);
                float r1 = __saturatef((v0.y + bv.y) * 0.16666667f + 0.5f);
                float r2 = __saturatef((v1.x + bv.x) * 0.16666667f + 0.5f);
                float r3 = __saturatef((v1.y + bv.y) * 0.16666667f + 0.5f);
                float2 h0 = *reinterpret_cast<const float2*>(hp + (size_t)(blockRow + rl) * HID + cb);
                float2 h1 = *reinterpret_cast<const float2*>(hp + (size_t)(blockRow + rl + 8) * HID + cb);
                int un = (INP + n0 + nt * 8) >> 3;
                int wo = ((un ^ r7) << 2) + kq;
                Asu[rl * AROWW + wo]       = h2pack(r0 * h0.x, r1 * h0.y);
                Asu[(rl + 8) * AROWW + wo] = h2pack(r2 * h1.x, r3 * h1.y);
            }
        }
    }
    __syncthreads();

    // ================= pass 3: htilde (fp32 acc); h_next = z*h + (1-z)*hardtanh(.) ======
    float acc[4][4][4];
    gemm_pass(rowb, usel7, wscratch + 2 * NCH * CHW, acc, n0, rq, kq);
    #pragma unroll
    for (int mt = 0; mt < 4; mt++) {
        int rl = mt * 16 + rq;
        #pragma unroll
        for (int nt = 0; nt < 4; nt++) {
            int cb = n0 + nt * 8 + (kq << 1);
            float2 bv = *reinterpret_cast<const float2*>(bh + cb);
            size_t o0 = (size_t)(blockRow + rl) * HID + cb;
            size_t o1 = (size_t)(blockRow + rl + 8) * HID + cb;
            int zc = (cb >> 1);
            float2 zz0 = h2unpack(Zsu[zoff(rl, zc)]);
            float2 zz1 = h2unpack(Zsu[zoff(rl + 8, zc)]);
            float2 hh0 = *reinterpret_cast<const float2*>(hp + o0);
            float2 hh1 = *reinterpret_cast<const float2*>(hp + o1);
            float t0 = fminf(fmaxf(acc[mt][nt][0] + bv.x, -1.f), 1.f);
            float t1 = fminf(fmaxf(acc[mt][nt][1] + bv.y, -1.f), 1.f);
            float t2 = fminf(fmaxf(acc[mt][nt][2] + bv.x, -1.f), 1.f);
            float t3 = fminf(fmaxf(acc[mt][nt][3] + bv.y, -1.f), 1.f);
            float2 r0, r1;
            r0.x = zz0.x * hh0.x + (1.f - zz0.x) * t0;
            r0.y = zz0.y * hh0.y + (1.f - zz0.y) * t1;
            r1.x = zz1.x * hh1.x + (1.f - zz1.x) * t2;
            r1.y = zz1.y * hh1.y + (1.f - zz1.y) * t3;
            *reinterpret_cast<float2*>(out + o0) = r0;
            *reinterpret_cast<float2*>(out + o1) = r1;
        }
    }
}

extern "C" void kernel_launch(void* const* d_in, const int* in_sizes, int n_in,
                              void* d_out, int out_size) {
    const float* x  = (const float*)d_in[0];
    const float* hp = (const float*)d_in[1];
    const float* Wz = (const float*)d_in[2];
    const float* bz = (const float*)d_in[3];
    const float* Wr = (const float*)d_in[4];
    const float* br = (const float*)d_in[5];
    const float* Wh = (const float*)d_in[6];
    const float* bh = (const float*)d_in[7];
    float* out = (float*)d_out;

    preconv_kernel<<<(3 * NCH * CHW + PTHREADS - 1) / PTHREADS, PTHREADS>>>(Wz, Wr, Wh);

    int batch = in_sizes[0] / INP;
    int grid = batch / TM;
    size_t smem = (size_t)(TM * AROWW + TM * ZROWW) * 4;   // 81920 B = 80 KB
    cudaFuncSetAttribute(gru_main_kernel,
                         cudaFuncAttributeMaxDynamicSharedMemorySize, (int)smem);
    gru_main_kernel<<<grid, THREADS, smem>>>(x, hp, bz, br, bh, out);
}

// round 17
// speedup vs baseline: 1.1687x; 1.1147x over previous
#include <cuda_runtime.h>
#include <cuda_fp16.h>
#include <cstdint>

#define THREADS  256        // 8 warps: warp grid 1m x 8n, warp tile 64x32
#define PTHREADS 256
#define TM       64         // batch rows per CTA
#define HID      256
#define INP      128
#define CAT      384
#define NCH      24         // K chunks of 16
#define CHW      2048       // uint32 words per chunk (256 n x 8 words)
#define AROWW    192        // words per A row (384 fp16), = 48 units of 16B
#define ZROWW    128        // words per z row (256 fp16)

// Pre-converted fp16 pair-interleaved weights.
// [zr combined: chunk c = 4096 words; word n*16 + 4*(p>>1) + (p&1) (+2 for Wr)]
// [Wh: 24 slots x 2048 words, word n*8 + p]; p (0..7) holds k-pair j = (p>>1)+(p&1)*4.
__device__ uint32_t wscratch[3 * NCH * CHW];

static __device__ __forceinline__ uint32_t smem_u32(const void* p) {
    uint32_t a;
    asm("{ .reg .u64 t; cvta.to.shared.u64 t, %1; cvt.u32.u64 %0, t; }" : "=r"(a) : "l"(p));
    return a;
}
static __device__ __forceinline__ uint32_t h2pack(float a, float b) {
    __half2 h = __floats2half2_rn(a, b);
    return *reinterpret_cast<uint32_t*>(&h);
}
static __device__ __forceinline__ float2 h2unpack(uint32_t u) {
    return __half22float2(*reinterpret_cast<__half2*>(&u));
}
static __device__ __forceinline__ void mma16(float* d, uint32_t a0, uint32_t a1,
                                             uint32_t a2, uint32_t a3,
                                             uint32_t b0, uint32_t b1) {
    asm volatile(
        "mma.sync.aligned.m16n8k16.row.col.f32.f16.f16.f32 "
        "{%0,%1,%2,%3}, {%4,%5,%6,%7}, {%8,%9}, {%0,%1,%2,%3};"
        : "+f"(d[0]), "+f"(d[1]), "+f"(d[2]), "+f"(d[3])
        : "r"(a0), "r"(a1), "r"(a2), "r"(a3), "r"(b0), "r"(b1));
}
// fp16-accumulator variant: D/C = 2 regs (half2 pairs), same element mapping as f32 d0..d3
static __device__ __forceinline__ void mma16h(uint32_t* d, const uint32_t (&a)[4],
                                              uint32_t b0, uint32_t b1) {
    asm volatile(
        "mma.sync.aligned.m16n8k16.row.col.f16.f16.f16.f16 "
        "{%0,%1}, {%2,%3,%4,%5}, {%6,%7}, {%0,%1};"
        : "+r"(d[0]), "+r"(d[1])
        : "r"(a[0]), "r"(a[1]), "r"(a[2]), "r"(a[3]), "r"(b0), "r"(b1));
}
static __device__ __forceinline__ void ldsm4(uint32_t (&a)[4], uint32_t saddr) {
    asm volatile("ldmatrix.sync.aligned.m8n8.x4.shared.b16 {%0,%1,%2,%3}, [%4];"
        : "=r"(a[0]), "=r"(a[1]), "=r"(a[2]), "=r"(a[3]) : "r"(saddr));
}
// z/h smem word offset: row rl, packed col zc (0..127), XOR swizzle conflict-free
static __device__ __forceinline__ int zoff(int rl, int zc) {
    return rl * ZROWW + (zc ^ ((rl & 7) << 2));
}

// ---------------- weight pre-conversion: fp32 -> fp16 images ----------------------------
__global__ void preconv_kernel(const float* __restrict__ Wz, const float* __restrict__ Wr,
                               const float* __restrict__ Wh) {
    int gid = blockIdx.x * PTHREADS + threadIdx.x;
    if (gid >= 3 * NCH * CHW) return;
    int w = gid / (NCH * CHW);
    int rem = gid - w * (NCH * CHW);
    int c = rem >> 11;            // / 2048
    int widx = rem & 2047;
    int n = widx >> 3;
    int p = widx & 7;
    int j = (p >> 1) + ((p & 1) << 2);
    int k = c * 16 + 2 * j;
    const float* W = (w == 0) ? Wz : (w == 1) ? Wr : Wh;
    uint32_t val = h2pack(W[(size_t)n * CAT + k], W[(size_t)n * CAT + k + 1]);
    size_t dst;
    if (w < 2)   // combined zr image: uint4 = (wz0, wz1, wr0, wr1) for (n, kq=p>>1)
        dst = (size_t)c * 4096 + n * 16 + 4 * (p >> 1) + (p & 1) + (w == 1 ? 2 : 0);
    else
        dst = (size_t)(2 * NCH) * CHW + (size_t)c * CHW + widx;
    wscratch[dst] = val;
}

#define UOFF(c) ((((2 * (c)) + usel) ^ l7) << 4)

// load the 4 combined zr fragments (uint4 = z-pair + r-pair) for one chunk
static __device__ __forceinline__ void ldb4(uint4 (&bf)[4], const uint4* __restrict__ p) {
    #pragma unroll
    for (int nt = 0; nt < 4; nt++) bf[nt] = __ldg(p + nt * 32);
}
// load the 4 B fragments (uint2) for one Wh chunk
static __device__ __forceinline__ void ldb(uint2 (&bf)[4], const uint2* __restrict__ p) {
    #pragma unroll
    for (int nt = 0; nt < 4; nt++) bf[nt] = __ldg(p + nt * 32);
}

// fused z+r chunk: one A fragment feeds 8 mma (4 z + 4 r), fp16 accumulators
static __device__ __forceinline__ void compute_chunk_zr(
    const uint32_t (&rowb)[4], uint32_t uoff_cur, uint32_t uoff_next,
    const uint4 (&bf)[4],
    uint32_t (&accz)[4][4][2], uint32_t (&accr)[4][4][2], uint32_t (&af)[4])
{
    uint32_t cur[4] = {af[0], af[1], af[2], af[3]};
    #pragma unroll
    for (int mt = 0; mt < 4; mt++) {
        uint32_t nxt[4];
        if (mt < 3) ldsm4(nxt, rowb[mt + 1] + uoff_cur);
        else        ldsm4(nxt, rowb[0] + uoff_next);
        #pragma unroll
        for (int nt = 0; nt < 4; nt++) {
            mma16h(accz[mt][nt], cur, bf[nt].x, bf[nt].y);
            mma16h(accr[mt][nt], cur, bf[nt].z, bf[nt].w);
        }
        cur[0] = nxt[0]; cur[1] = nxt[1]; cur[2] = nxt[2]; cur[3] = nxt[3];
    }
    af[0] = cur[0]; af[1] = cur[1]; af[2] = cur[2]; af[3] = cur[3];
}

// ---------------- fused z+r pass: combined LDG.128 B, 2 buffers -------------------------
static __device__ __forceinline__ void gemm_fused_zr(
    const uint32_t (&rowb)[4], uint32_t usel7, const uint32_t* __restrict__ wbase,
    uint32_t (&accz)[4][4][2], uint32_t (&accr)[4][4][2], int n0, int rq, int kq)
{
    #pragma unroll
    for (int mt = 0; mt < 4; mt++)
        #pragma unroll
        for (int nt = 0; nt < 4; nt++) {
            accz[mt][nt][0] = 0u; accz[mt][nt][1] = 0u;
            accr[mt][nt][0] = 0u; accr[mt][nt][1] = 0u;
        }

    // uint4 index for (chunk 0, n = n0+rq+nt*8, kq): word (n*16+4kq) / 4
    const uint4* __restrict__ Bg =
        reinterpret_cast<const uint4*>(wbase) + ((n0 + rq) * 4 + kq);
    const uint32_t usel = usel7 >> 8, l7 = usel7 & 7;

    uint4 b0[4], b1[4];
    ldb4(b0, Bg);
    uint32_t af[4];
    ldsm4(af, rowb[0] + UOFF(0));

    #pragma unroll 1
    for (int cc = 0; cc < 12; cc++) {
        int c = cc * 2;
        if (c + 1 < NCH) ldb4(b1, Bg + (size_t)(c + 1) * 1024);
        compute_chunk_zr(rowb, UOFF(c), UOFF(c + 1), b0, accz, accr, af);
        if (c + 2 < NCH) ldb4(b0, Bg + (size_t)(c + 2) * 1024);
        compute_chunk_zr(rowb, UOFF(c + 1), UOFF(c + 2 < NCH ? c + 2 : NCH - 1),
                         b1, accz, accr, af);
    }
}

// fp32-acc chunk (pass 3), A-fragment pipelined
static __device__ __forceinline__ void compute_chunk(
    const uint32_t (&rowb)[4], uint32_t uoff_cur, uint32_t uoff_next,
    const uint2 (&bf)[4], float (&acc)[4][4][4], uint32_t (&af)[4])
{
    uint32_t cur[4] = {af[0], af[1], af[2], af[3]};
    #pragma unroll
    for (int mt = 0; mt < 4; mt++) {
        uint32_t nxt[4];
        if (mt < 3) ldsm4(nxt, rowb[mt + 1] + uoff_cur);
        else        ldsm4(nxt, rowb[0] + uoff_next);
        #pragma unroll
        for (int nt = 0; nt < 4; nt++)
            mma16(acc[mt][nt], cur[0], cur[1], cur[2], cur[3], bf[nt].x, bf[nt].y);
        cur[0] = nxt[0]; cur[1] = nxt[1]; cur[2] = nxt[2]; cur[3] = nxt[3];
    }
    af[0] = cur[0]; af[1] = cur[1]; af[2] = cur[2]; af[3] = cur[3];
}

// ---------------- pass 3 GEMM: fp32 acc, 4 B buffers, distance-3 ------------------------
static __device__ __forceinline__ void gemm_pass(
    const uint32_t (&rowb)[4], uint32_t usel7, const uint32_t* __restrict__ wbase,
    float (&acc)[4][4][4], int n0, int rq, int kq)
{
    #pragma unroll
    for (int mt = 0; mt < 4; mt++)
        #pragma unroll
        for (int nt = 0; nt < 4; nt++)
            #pragma unroll
            for (int q = 0; q < 4; q++) acc[mt][nt][q] = 0.f;

    const uint2* __restrict__ Bg =
        reinterpret_cast<const uint2*>(wbase) + ((n0 + rq) * 4 + kq);
    const uint32_t usel = usel7 >> 8, l7 = usel7 & 7;

    uint2 b0[4], b1[4], b2[4], b3[4];
    ldb(b0, Bg);
    ldb(b1, Bg + 1024);
    ldb(b2, Bg + 2048);
    uint32_t af[4];
    ldsm4(af, rowb[0] + UOFF(0));

    #pragma unroll 1
    for (int cc = 0; cc < 6; cc++) {
        int c = cc * 4;
        if (c + 3 < NCH) ldb(b3, Bg + (size_t)(c + 3) * 1024);
        compute_chunk(rowb, UOFF(c + 0), UOFF(c + 1), b0, acc, af);
        if (c + 4 < NCH) ldb(b0, Bg + (size_t)(c + 4) * 1024);
        compute_chunk(rowb, UOFF(c + 1), UOFF(c + 2), b1, acc, af);
        if (c + 5 < NCH) ldb(b1, Bg + (size_t)(c + 5) * 1024);
        compute_chunk(rowb, UOFF(c + 2), UOFF(c + 3), b2, acc, af);
        if (c + 6 < NCH) ldb(b2, Bg + (size_t)(c + 6) * 1024);
        compute_chunk(rowb, UOFF(c + 3), UOFF(c + 4 < NCH ? c + 4 : NCH - 1), b3, acc, af);
    }
}

// ---------------- fused GRU kernel ------------------------------------------------------
__global__ void __launch_bounds__(THREADS, 2) gru_main_kernel(
    const float* __restrict__ x, const float* __restrict__ hp,
    const float* __restrict__ bz, const float* __restrict__ br,
    const float* __restrict__ bh, float* __restrict__ out)
{
    extern __shared__ uint32_t Asu[];         // 64 rows x 48 units(16B), unit u at u^(r&7)
    uint32_t* Zsu = Asu + TM * AROWW;         // 64*128 words (fp16x2 z stash)
    uint32_t* Hsu = Zsu + TM * ZROWW;         // 64*128 words (fp16x2 h stash)

    const int tid  = threadIdx.x;
    const int lane = tid & 31;
    const int warp = tid >> 5;
    const int n0   = warp * 32;
    const int rq   = lane >> 2;
    const int kq   = lane & 3;
    const int blockRow = blockIdx.x * TM;

    // ---- fill A smem (fp16 ih, unit-XOR swizzle) + h stash (fp16, zoff swizzle) ----
    #pragma unroll 1
    for (int it = 0; it < 6; it++) {
        int idx = it * THREADS + tid;          // 0 .. 1535 groups
        int row = idx / 24;
        int g   = idx - row * 24;
        int k0  = g * 16;
        const float* src = (k0 < INP) ? (x + (size_t)(blockRow + row) * INP + k0)
                                      : (hp + (size_t)(blockRow + row) * HID + (k0 - INP));
        float4 v0 = *reinterpret_cast<const float4*>(src);
        float4 v1 = *reinterpret_cast<const float4*>(src + 4);
        float4 v2 = *reinterpret_cast<const float4*>(src + 8);
        float4 v3 = *reinterpret_cast<const float4*>(src + 12);
        uint4 u0, u1;   // natural order pairs
        u0.x = h2pack(v0.x, v0.y); u0.y = h2pack(v0.z, v0.w);
        u0.z = h2pack(v1.x, v1.y); u0.w = h2pack(v1.z, v1.w);
        u1.x = h2pack(v2.x, v2.y); u1.y = h2pack(v2.z, v2.w);
        u1.z = h2pack(v3.x, v3.y); u1.w = h2pack(v3.z, v3.w);
        int r7 = row & 7;
        int un = g * 2;
        *reinterpret_cast<uint4*>(Asu + row * AROWW + ((un ^ r7) << 2))       = u0;
        *reinterpret_cast<uint4*>(Asu + row * AROWW + (((un + 1) ^ r7) << 2)) = u1;
        if (k0 >= INP) {    // h stash: cols (k0-128)..(k0-113), word base (k0-128)/2
            int zcb = (k0 - INP) >> 1;
            *reinterpret_cast<uint4*>(Hsu + zoff(row, zcb))     = u0;
            *reinterpret_cast<uint4*>(Hsu + zoff(row, zcb + 4)) = u1;
        }
    }
    __syncthreads();

    uint32_t abase = smem_u32(Asu);
    uint32_t rowb[4];
    #pragma unroll
    for (int mt = 0; mt < 4; mt++)
        rowb[mt] = abase + (mt * 16 + (lane & 15)) * (AROWW * 4);
    const uint32_t usel7 = (((uint32_t)(lane >> 4) & 1) << 8) | (uint32_t)(lane & 7);

    // ================= fused pass: z & r preacts (fp16 acc) =============================
    {
        uint32_t accz[4][4][2], accr[4][4][2];
        gemm_fused_zr(rowb, usel7, wscratch, accz, accr, n0, rq, kq);

        // z epilogue -> Zsu (no A access; no sync needed yet)
        #pragma unroll
        for (int mt = 0; mt < 4; mt++) {
            int rl = mt * 16 + rq;
            #pragma unroll
            for (int nt = 0; nt < 4; nt++) {
                int cb = n0 + nt * 8 + (kq << 1);
                float2 bv = *reinterpret_cast<const float2*>(bz + cb);
                float2 v0 = h2unpack(accz[mt][nt][0]);   // row rl,  cols cb, cb+1
                float2 v1 = h2unpack(accz[mt][nt][1]);   // row rl+8
                float z0 = __saturatef((v0.x + bv.x) * 0.16666667f + 0.5f);
                float z1 = __saturatef((v0.y + bv.y) * 0.16666667f + 0.5f);
                float z2 = __saturatef((v1.x + bv.x) * 0.16666667f + 0.5f);
                float z3 = __saturatef((v1.y + bv.y) * 0.16666667f + 0.5f);
                int zc = (cb >> 1);
                Zsu[zoff(rl, zc)]     = h2pack(z0, z1);
                Zsu[zoff(rl + 8, zc)] = h2pack(z2, z3);
            }
        }

        __syncthreads();   // all warps done reading A in fused pass

        // r epilogue: A_h := fp16(r * h), h from smem stash
        #pragma unroll
        for (int mt = 0; mt < 4; mt++) {
            int rl = mt * 16 + rq;
            int r7 = rl & 7;
            #pragma unroll
            for (int nt = 0; nt < 4; nt++) {
                int cb = n0 + nt * 8 + (kq << 1);
                float2 bv = *reinterpret_cast<const float2*>(br + cb);
                float2 v0 = h2unpack(accr[mt][nt][0]);
                float2 v1 = h2unpack(accr[mt][nt][1]);
                float r0 = __saturatef((v0.x + bv.x) * 0.16666667f + 0.5f);
                float r1 = __saturatef((v0.y + bv.y) * 0.16666667f + 0.5f);
                float r2 = __saturatef((v1.x + bv.x) * 0.16666667f + 0.5f);
                float r3 = __saturatef((v1.y + bv.y) * 0.16666667f + 0.5f);
                int zc = (cb >> 1);
                float2 h0 = h2unpack(Hsu[zoff(rl, zc)]);
                float2 h1 = h2unpack(Hsu[zoff(rl + 8, zc)]);
                int un = (INP + n0 + nt * 8) >> 3;
                int wo = ((un ^ r7) << 2) + kq;
                Asu[rl * AROWW + wo]       = h2pack(r0 * h0.x, r1 * h0.y);
                Asu[(rl + 8) * AROWW + wo] = h2pack(r2 * h1.x, r3 * h1.y);
            }
        }
    }
    __syncthreads();

    // ================= pass 3: htilde (fp32 acc); h_next = z*h + (1-z)*hardtanh(.) ======
    float acc[4][4][4];
    gemm_pass(rowb, usel7, wscratch + 2 * NCH * CHW, acc, n0, rq, kq);
    #pragma unroll
    for (int mt = 0; mt < 4; mt++) {
        int rl = mt * 16 + rq;
        #pragma unroll
        for (int nt = 0; nt < 4; nt++) {
            int cb = n0 + nt * 8 + (kq << 1);
            float2 bv = *reinterpret_cast<const float2*>(bh + cb);
            size_t o0 = (size_t)(blockRow + rl) * HID + cb;
            size_t o1 = (size_t)(blockRow + rl + 8) * HID + cb;
            int zc = (cb >> 1);
            float2 zz0 = h2unpack(Zsu[zoff(rl, zc)]);
            float2 zz1 = h2unpack(Zsu[zoff(rl + 8, zc)]);
            float2 hh0 = h2unpack(Hsu[zoff(rl, zc)]);
            float2 hh1 = h2unpack(Hsu[zoff(rl + 8, zc)]);
            float t0 = fminf(fmaxf(acc[mt][nt][0] + bv.x, -1.f), 1.f);
            float t1 = fminf(fmaxf(acc[mt][nt][1] + bv.y, -1.f), 1.f);
            float t2 = fminf(fmaxf(acc[mt][nt][2] + bv.x, -1.f), 1.f);
            float t3 = fminf(fmaxf(acc[mt][nt][3] + bv.y, -1.f), 1.f);
            float2 r0, r1;
            r0.x = zz0.x * hh0.x + (1.f - zz0.x) * t0;
            r0.y = zz0.y * hh0.y + (1.f - zz0.y) * t1;
            r1.x = zz1.x * hh1.x + (1.f - zz1.x) * t2;
            r1.y = zz1.y * hh1.y + (1.f - zz1.y) * t3;
            *reinterpret_cast<float2*>(out + o0) = r0;
            *reinterpret_cast<float2*>(out + o1) = r1;
        }
    }
}

extern "C" void kernel_launch(void* const* d_in, const int* in_sizes, int n_in,
                              void* d_out, int out_size) {
    const float* x  = (const float*)d_in[0];
    const float* hp = (const float*)d_in[1];
    const float* Wz = (const float*)d_in[2];
    const float* bz = (const float*)d_in[3];
    const float* Wr = (const float*)d_in[4];
    const float* br = (const float*)d_in[5];
    const float* Wh = (const float*)d_in[6];
    const float* bh = (const float*)d_in[7];
    float* out = (float*)d_out;

    preconv_kernel<<<(3 * NCH * CHW + PTHREADS - 1) / PTHREADS, PTHREADS>>>(Wz, Wr, Wh);

    int batch = in_sizes[0] / INP;
    int grid = batch / TM;
    size_t smem = (size_t)(TM * AROWW + 2 * TM * ZROWW) * 4;   // 114688 B = 112 KB
    cudaFuncSetAttribute(gru_main_kernel,
                         cudaFuncAttributeMaxDynamicSharedMemorySize, (int)smem);
    gru_main_kernel<<<grid, THREADS, smem>>>(x, hp, bz, br, bh, out);
}